// round 5
// baseline (speedup 1.0000x reference)
#include <cuda_runtime.h>
#include <cuda_fp16.h>
#include <cstdint>

// Problem constants (fixed by setup_inputs)
#define BATCH 8
#define HDIM  64
#define WDIM  64
#define CDIM  128
#define FDIM  128
#define KNUM  9
#define NPIX  (BATCH * HDIM * WDIM)      // 32768
#define PIX_PER_CTA 128
#define NCTA  (NPIX / PIX_PER_CTA)       // 256

#define PADA 136                          // halves per SMEM row (272 B) -> conflict-free ldmatrix
#define TILE_BYTES (128 * PADA * 2)       // 34816
#define SM_A0 0
#define SM_A1 TILE_BYTES
#define SM_B0 (2 * TILE_BYTES)
#define SM_B1 (3 * TILE_BYTES)
#define SM_BIAS (4 * TILE_BYTES)
#define SMEM_BYTES (SM_BIAS + 512)        // 139776

// TF build(): stack(meshgrid(ij)).reshape(-1,2) pairs:
// (0,0),(0,1),(1,1),(2,2),(2,0),(1,2),(0,1),(2,0),(1,2)
static __device__ const float KOFF_I[KNUM] = {0.f, 0.f, 1.f, 2.f, 2.f, 1.f, 0.f, 2.f, 1.f};
static __device__ const float KOFF_J[KNUM] = {0.f, 1.f, 1.f, 2.f, 0.f, 2.f, 1.f, 0.f, 2.f};

// Pre-transposed fp16 weights: g_Wh[kn][f][c], 9*128*128 halves = 288 KB.
__device__ __align__(16) __half g_Wh[KNUM * 128 * 128];

__global__ void prep_weights_kernel(const float* __restrict__ Wsrc) {
    int idx = blockIdx.x * 256 + threadIdx.x;
    if (idx >= KNUM * 128 * 128) return;
    int kn = idx >> 14;
    int r  = idx & 16383;
    int f  = r >> 7;    // output-feature row (N)
    int c  = r & 127;   // channel col (K)
    g_Wh[kn * 16384 + f * 128 + c] = __float2half_rn(Wsrc[(kn * 128 + c) * 128 + f]);
}

__device__ __forceinline__ uint32_t smem_u32(const void* p) {
    uint32_t a;
    asm("{ .reg .u64 t; cvta.to.shared.u64 t, %1; cvt.u32.u64 %0, t; }" : "=r"(a) : "l"(p));
    return a;
}

__device__ __forceinline__ void ldsm4(uint32_t r[4], uint32_t addr) {
    asm volatile("ldmatrix.sync.aligned.m8n8.x4.shared.b16 {%0,%1,%2,%3}, [%4];"
                 : "=r"(r[0]), "=r"(r[1]), "=r"(r[2]), "=r"(r[3]) : "r"(addr));
}

__device__ __forceinline__ void mma16816(float d[4], const uint32_t a[4],
                                         uint32_t b0, uint32_t b1) {
    asm volatile(
        "mma.sync.aligned.m16n8k16.row.col.f32.f16.f16.f32 "
        "{%0,%1,%2,%3}, {%4,%5,%6,%7}, {%8,%9}, {%0,%1,%2,%3};"
        : "+f"(d[0]), "+f"(d[1]), "+f"(d[2]), "+f"(d[3])
        : "r"(a[0]), "r"(a[1]), "r"(a[2]), "r"(a[3]), "r"(b0), "r"(b1));
}

__device__ __forceinline__ void cpa16(uint32_t dst, const void* src) {
    asm volatile("cp.async.cg.shared.global [%0], [%1], 16;" :: "r"(dst), "l"(src));
}
#define CP_COMMIT asm volatile("cp.async.commit_group;" ::: "memory")
#define CP_WAIT0  asm volatile("cp.async.wait_group 0;" ::: "memory")

// Stage one 128x128 fp16 weight tile into padded SMEM via cp.async (32 KB).
__device__ __forceinline__ void stage_B(uint32_t Bb, const __half* src, int tid) {
    #pragma unroll
    for (int i = 0; i < 8; i++) {
        int e = i * 256 + tid;          // 16B-chunk index, 0..2047
        int row = e >> 4;
        int c16 = e & 15;
        cpa16(Bb + row * 272 + c16 * 16, src + row * 128 + c16 * 8);
    }
}

__global__ __launch_bounds__(256, 1)
void deform_conv_kernel(const float* __restrict__ xin,
                        const float* __restrict__ off,
                        const float* __restrict__ bias,
                        float* __restrict__ out) {
    extern __shared__ char smem[];
    uint32_t sb = smem_u32(smem);
    float* bsm = (float*)(smem + SM_BIAS);

    const int tid = threadIdx.x;
    const int wid = tid >> 5;
    const int lid = tid & 31;
    const int g   = lid >> 2;
    const int tig = lid & 3;
    const int wm  = wid & 3;    // warp row block (32 pixels)
    const int wn  = wid >> 2;   // warp col block (64 F)
    const int pix0 = blockIdx.x * PIX_PER_CTA;

    if (tid < 128) bsm[tid] = bias[tid];

    // ---- Prologue: stage B0, sample chunk 0 into As[0] ----
    stage_B(sb + SM_B0, g_Wh, tid);
    CP_COMMIT;
    {
        const float ki = KOFF_I[0], kj = KOFF_J[0];
        #pragma unroll 4
        for (int j = 0; j < 16; j++) {
            int p = wid * 16 + j;
            int P = pix0 + p;
            int bb = P >> 12, hh = (P >> 6) & 63, ww = P & 63;
            float offr = __ldg(&off[P * 18 + 0]);
            float offc = __ldg(&off[P * 18 + 1]);
            float y  = fminf(fmaxf((float)(hh - 1) + ki + offr, 0.0f), 63.0f);
            float xf = fminf(fmaxf((float)(ww - 1) + kj + offc, 0.0f), 63.0f);
            float y0f = floorf(y), x0f = floorf(xf);
            int y0 = (int)y0f, y1 = (int)ceilf(y);
            int x0 = (int)x0f, x1 = (int)ceilf(xf);
            float fy = y - y0f, fx = xf - x0f;
            const float4* base = (const float4*)xin + (size_t)bb * 131072;
            float4 lt = __ldg(&base[(y0 * 64 + x0) * 32 + lid]);
            float4 rt = __ldg(&base[(y1 * 64 + x0) * 32 + lid]);
            float4 lb = __ldg(&base[(y0 * 64 + x1) * 32 + lid]);
            float4 rb = __ldg(&base[(y1 * 64 + x1) * 32 + lid]);
            float4 vt, vb, v;
            vt.x = fmaf(rt.x - lt.x, fy, lt.x); vt.y = fmaf(rt.y - lt.y, fy, lt.y);
            vt.z = fmaf(rt.z - lt.z, fy, lt.z); vt.w = fmaf(rt.w - lt.w, fy, lt.w);
            vb.x = fmaf(rb.x - lb.x, fy, lb.x); vb.y = fmaf(rb.y - lb.y, fy, lb.y);
            vb.z = fmaf(rb.z - lb.z, fy, lb.z); vb.w = fmaf(rb.w - lb.w, fy, lb.w);
            v.x = fmaf(vb.x - vt.x, fx, vt.x); v.y = fmaf(vb.y - vt.y, fx, vt.y);
            v.z = fmaf(vb.z - vt.z, fx, vt.z); v.w = fmaf(vb.w - vt.w, fx, vt.w);
            half2 h01 = __floats2half2_rn(v.x, v.y);
            half2 h23 = __floats2half2_rn(v.z, v.w);
            uint2 st = make_uint2(*(uint32_t*)&h01, *(uint32_t*)&h23);
            *(uint2*)(smem + SM_A0 + p * 272 + lid * 8) = st;
        }
    }
    CP_WAIT0;
    __syncthreads();

    float acc[2][8][4];
    #pragma unroll
    for (int mt = 0; mt < 2; mt++)
        #pragma unroll
        for (int nt = 0; nt < 8; nt++)
            #pragma unroll
            for (int q = 0; q < 4; q++) acc[mt][nt][q] = 0.0f;

    // Prefetch offsets for chunk 1 (lane l holds comp (l&1) of pixel wid*16+(l>>1))
    float offv;
    { int P = pix0 + wid * 16 + (lid >> 1); offv = __ldg(&off[P * 18 + 2 + (lid & 1)]); }

    int cur = 0;
    for (int n = 0; n < KNUM; n++) {
        const bool pre = (n + 1 < KNUM);
        const uint32_t Ab  = sb + (cur ? SM_A1 : SM_A0);
        const uint32_t Bb  = sb + (cur ? SM_B1 : SM_B0);
        const int      AbnOff = (cur ? SM_A0 : SM_A1);
        const uint32_t Bbn = sb + (cur ? SM_B0 : SM_B1);

        if (pre) { stage_B(Bbn, g_Wh + (n + 1) * 16384, tid); CP_COMMIT; }

        float offv_next = 0.0f;
        if (n + 2 < KNUM) {
            int P = pix0 + wid * 16 + (lid >> 1);
            offv_next = __ldg(&off[P * 18 + 2 * (n + 2) + (lid & 1)]);
        }

        const float ki = KOFF_I[pre ? (n + 1) : 0];
        const float kj = KOFF_J[pre ? (n + 1) : 0];

        #pragma unroll
        for (int sub = 0; sub < 4; sub++) {
            float4 crn[4][4];
            float fys[4], fxs[4];
            // --- issue next-chunk gathers (consumed after the MMA block) ---
            if (pre) {
                #pragma unroll
                for (int j = 0; j < 4; j++) {
                    int pl = sub * 4 + j;
                    int P = pix0 + wid * 16 + pl;
                    float offr = __shfl_sync(0xffffffffu, offv, pl * 2);
                    float offc = __shfl_sync(0xffffffffu, offv, pl * 2 + 1);
                    int bb = P >> 12, hh = (P >> 6) & 63, ww = P & 63;
                    float y  = fminf(fmaxf((float)(hh - 1) + ki + offr, 0.0f), 63.0f);
                    float xf = fminf(fmaxf((float)(ww - 1) + kj + offc, 0.0f), 63.0f);
                    float y0f = floorf(y), x0f = floorf(xf);
                    int y0 = (int)y0f, y1 = (int)ceilf(y);
                    int x0 = (int)x0f, x1 = (int)ceilf(xf);
                    fys[j] = y - y0f; fxs[j] = xf - x0f;
                    const float4* base = (const float4*)xin + (size_t)bb * 131072;
                    crn[j][0] = __ldg(&base[(y0 * 64 + x0) * 32 + lid]);
                    crn[j][1] = __ldg(&base[(y1 * 64 + x0) * 32 + lid]);
                    crn[j][2] = __ldg(&base[(y0 * 64 + x1) * 32 + lid]);
                    crn[j][3] = __ldg(&base[(y1 * 64 + x1) * 32 + lid]);
                }
            }
            // --- MMA: 2 k-steps of 16 on current buffers ---
            #pragma unroll
            for (int kk = 0; kk < 2; kk++) {
                int k0b = (sub * 2 + kk) * 32;   // k offset in bytes (16 halves)
                uint32_t a[2][4], b[4][4];
                #pragma unroll
                for (int mt = 0; mt < 2; mt++)
                    ldsm4(a[mt], Ab + (wm * 32 + mt * 16 + (lid & 15)) * 272
                                    + k0b + (lid >> 4) * 16);
                #pragma unroll
                for (int q = 0; q < 4; q++)
                    ldsm4(b[q], Bb + (wn * 64 + q * 16 + (lid & 15)) * 272
                                   + k0b + (lid >> 4) * 16);
                #pragma unroll
                for (int mt = 0; mt < 2; mt++)
                    #pragma unroll
                    for (int q = 0; q < 4; q++) {
                        mma16816(acc[mt][2 * q],     a[mt], b[q][0], b[q][2]);
                        mma16816(acc[mt][2 * q + 1], a[mt], b[q][1], b[q][3]);
                    }
            }
            // --- interpolate + store next-chunk A tile ---
            if (pre) {
                #pragma unroll
                for (int j = 0; j < 4; j++) {
                    int pl = sub * 4 + j;
                    float fy = fys[j], fx = fxs[j];
                    float4 lt = crn[j][0], rt = crn[j][1], lb = crn[j][2], rb = crn[j][3];
                    float4 vt, vb, v;
                    vt.x = fmaf(rt.x - lt.x, fy, lt.x); vt.y = fmaf(rt.y - lt.y, fy, lt.y);
                    vt.z = fmaf(rt.z - lt.z, fy, lt.z); vt.w = fmaf(rt.w - lt.w, fy, lt.w);
                    vb.x = fmaf(rb.x - lb.x, fy, lb.x); vb.y = fmaf(rb.y - lb.y, fy, lb.y);
                    vb.z = fmaf(rb.z - lb.z, fy, lb.z); vb.w = fmaf(rb.w - lb.w, fy, lb.w);
                    v.x = fmaf(vb.x - vt.x, fx, vt.x); v.y = fmaf(vb.y - vt.y, fx, vt.y);
                    v.z = fmaf(vb.z - vt.z, fx, vt.z); v.w = fmaf(vb.w - vt.w, fx, vt.w);
                    half2 h01 = __floats2half2_rn(v.x, v.y);
                    half2 h23 = __floats2half2_rn(v.z, v.w);
                    uint2 st = make_uint2(*(uint32_t*)&h01, *(uint32_t*)&h23);
                    *(uint2*)(smem + AbnOff + (wid * 16 + pl) * 272 + lid * 8) = st;
                }
            }
        }
        if (pre) CP_WAIT0;
        __syncthreads();
        offv = offv_next;
        cur ^= 1;
    }

    // ---- Epilogue: add bias, store fp32 output ----
    #pragma unroll
    for (int mt = 0; mt < 2; mt++) {
        #pragma unroll
        for (int nt = 0; nt < 8; nt++) {
            int col = wn * 64 + nt * 8 + tig * 2;
            float b0 = bsm[col], b1 = bsm[col + 1];
            int row = pix0 + wm * 32 + mt * 16 + g;
            *(float2*)(out + (size_t)row * FDIM + col) =
                make_float2(acc[mt][nt][0] + b0, acc[mt][nt][1] + b1);
            *(float2*)(out + (size_t)(row + 8) * FDIM + col) =
                make_float2(acc[mt][nt][2] + b0, acc[mt][nt][3] + b1);
        }
    }
}

extern "C" void kernel_launch(void* const* d_in, const int* in_sizes, int n_in,
                              void* d_out, int out_size) {
    const float* x   = (const float*)d_in[0];
    const float* off = (const float*)d_in[1];
    const float* Wk  = (const float*)d_in[2];
    const float* b   = (const float*)d_in[3];
    float* out = (float*)d_out;

    cudaFuncSetAttribute(deform_conv_kernel,
                         cudaFuncAttributeMaxDynamicSharedMemorySize, SMEM_BYTES);

    prep_weights_kernel<<<(KNUM * 128 * 128 + 255) / 256, 256>>>(Wk);
    deform_conv_kernel<<<NCTA, 256, SMEM_BYTES>>>(x, off, b, out);
}

// round 6
// speedup vs baseline: 1.5497x; 1.5497x over previous
#include <cuda_runtime.h>
#include <cuda_fp16.h>
#include <cstdint>

// Problem constants (fixed by setup_inputs)
#define BATCH 8
#define HDIM  64
#define WDIM  64
#define CDIM  128
#define FDIM  128
#define KNUM  9
#define NPIX  (BATCH * HDIM * WDIM)      // 32768
#define PIX_PER_CTA 128
#define NCTA  (NPIX / PIX_PER_CTA)       // 256

#define ROWB 272                          // bytes per SMEM tile row (136 halves) -> conflict-free
#define TILE_BYTES (128 * ROWB)           // 34816
#define SM_A 0
#define SM_B TILE_BYTES
#define SM_BIAS (2 * TILE_BYTES)          // 69632
#define SMEM_BYTES (SM_BIAS + 512)        // 70144  -> 2 CTAs/SM

// TF build(): stack(meshgrid(ij)).reshape(-1,2) pairs:
// (0,0),(0,1),(1,1),(2,2),(2,0),(1,2),(0,1),(2,0),(1,2)
static __device__ const float KOFF_I[KNUM] = {0.f, 0.f, 1.f, 2.f, 2.f, 1.f, 0.f, 2.f, 1.f};
static __device__ const float KOFF_J[KNUM] = {0.f, 1.f, 1.f, 2.f, 0.f, 2.f, 1.f, 0.f, 2.f};

// Pre-transposed fp16 weights: g_Wh[kn][f][c], 9*128*128 halves = 288 KB (L2-resident).
__device__ __align__(16) __half g_Wh[KNUM * 128 * 128];

__global__ void prep_weights_kernel(const float* __restrict__ Wsrc) {
    int idx = blockIdx.x * 256 + threadIdx.x;
    if (idx >= KNUM * 128 * 128) return;
    int kn = idx >> 14;
    int r  = idx & 16383;
    int f  = r >> 7;    // output-feature row (N)
    int c  = r & 127;   // channel col (K)
    g_Wh[kn * 16384 + f * 128 + c] = __float2half_rn(Wsrc[(kn * 128 + c) * 128 + f]);
}

__device__ __forceinline__ uint32_t smem_u32(const void* p) {
    uint32_t a;
    asm("{ .reg .u64 t; cvta.to.shared.u64 t, %1; cvt.u32.u64 %0, t; }" : "=r"(a) : "l"(p));
    return a;
}

__device__ __forceinline__ void ldsm4(uint32_t r[4], uint32_t addr) {
    asm volatile("ldmatrix.sync.aligned.m8n8.x4.shared.b16 {%0,%1,%2,%3}, [%4];"
                 : "=r"(r[0]), "=r"(r[1]), "=r"(r[2]), "=r"(r[3]) : "r"(addr));
}

__device__ __forceinline__ void mma16816(float d[4], const uint32_t a[4],
                                         uint32_t b0, uint32_t b1) {
    asm volatile(
        "mma.sync.aligned.m16n8k16.row.col.f32.f16.f16.f32 "
        "{%0,%1,%2,%3}, {%4,%5,%6,%7}, {%8,%9}, {%0,%1,%2,%3};"
        : "+f"(d[0]), "+f"(d[1]), "+f"(d[2]), "+f"(d[3])
        : "r"(a[0]), "r"(a[1]), "r"(a[2]), "r"(a[3]), "r"(b0), "r"(b1));
}

__device__ __forceinline__ void cpa16(uint32_t dst, const void* src) {
    asm volatile("cp.async.cg.shared.global [%0], [%1], 16;" :: "r"(dst), "l"(src));
}
#define CP_COMMIT asm volatile("cp.async.commit_group;" ::: "memory")
#define CP_WAIT0  asm volatile("cp.async.wait_group 0;" ::: "memory")

__global__ __launch_bounds__(256, 2)
void deform_conv_kernel(const float* __restrict__ xin,
                        const float* __restrict__ off,
                        const float* __restrict__ bias,
                        float* __restrict__ out) {
    extern __shared__ char smem[];
    uint32_t sb = smem_u32(smem);
    float* bsm = (float*)(smem + SM_BIAS);

    const int tid = threadIdx.x;
    const int wid = tid >> 5;
    const int lid = tid & 31;
    const int g   = lid >> 2;
    const int tig = lid & 3;
    const int wm  = wid & 3;    // warp row block (32 pixels)
    const int wn  = wid >> 2;   // warp col block (64 F)
    const int pix0 = blockIdx.x * PIX_PER_CTA;

    if (tid < 128) bsm[tid] = bias[tid];

    float acc[2][8][4];
    #pragma unroll
    for (int mt = 0; mt < 2; mt++)
        #pragma unroll
        for (int nt = 0; nt < 8; nt++)
            #pragma unroll
            for (int q = 0; q < 4; q++) acc[mt][nt][q] = 0.0f;

    // Fragment base addresses (constant across chunks)
    const uint32_t Abase = sb + SM_A + (wm * 32 + (lid & 15)) * ROWB + (lid >> 4) * 16;
    const uint32_t Bbase = sb + SM_B + (wn * 64 + (lid & 15)) * ROWB + (lid >> 4) * 16;

    for (int n = 0; n < KNUM; n++) {
        // ---- Stage B: cp.async copy of pre-rounded fp16 Wt[n] into padded SMEM ----
        {
            const __half* src = g_Wh + n * 16384;
            #pragma unroll
            for (int i = 0; i < 8; i++) {
                int e = i * 256 + tid;          // 16B-chunk index, 0..2047
                int row = e >> 4;
                int c16 = e & 15;
                cpa16(sb + SM_B + row * ROWB + c16 * 16, src + row * 128 + c16 * 8);
            }
            CP_COMMIT;
        }

        // ---- Stage A: bilinear sample 128 pixels x 128 channels (fp16 out) ----
        // One warp per pixel (16 pixels/warp); each lane handles 4 channels.
        const float ki = KOFF_I[n];
        const float kj = KOFF_J[n];
        #pragma unroll 2
        for (int i = 0; i < 16; i++) {
            int p = wid * 16 + i;          // local pixel 0..127
            int P = pix0 + p;              // global pixel
            int bb = P >> 12;
            int hh = (P >> 6) & 63;
            int ww = P & 63;
            float offr = __ldg(&off[P * 18 + 2 * n]);
            float offc = __ldg(&off[P * 18 + 2 * n + 1]);
            float y  = fminf(fmaxf((float)(hh - 1) + ki + offr, 0.0f), 63.0f);
            float xf = fminf(fmaxf((float)(ww - 1) + kj + offc, 0.0f), 63.0f);
            float y0f = floorf(y), x0f = floorf(xf);
            int y0 = (int)y0f, y1 = (int)ceilf(y);
            int x0 = (int)x0f, x1 = (int)ceilf(xf);
            float fy = y - y0f, fx = xf - x0f;

            const float4* base = (const float4*)xin + (size_t)bb * 131072;
            float4 lt = __ldg(&base[(y0 * 64 + x0) * 32 + lid]);
            float4 rt = __ldg(&base[(y1 * 64 + x0) * 32 + lid]);
            float4 lb = __ldg(&base[(y0 * 64 + x1) * 32 + lid]);
            float4 rb = __ldg(&base[(y1 * 64 + x1) * 32 + lid]);

            float4 vt, vb, v;
            vt.x = fmaf(rt.x - lt.x, fy, lt.x); vt.y = fmaf(rt.y - lt.y, fy, lt.y);
            vt.z = fmaf(rt.z - lt.z, fy, lt.z); vt.w = fmaf(rt.w - lt.w, fy, lt.w);
            vb.x = fmaf(rb.x - lb.x, fy, lb.x); vb.y = fmaf(rb.y - lb.y, fy, lb.y);
            vb.z = fmaf(rb.z - lb.z, fy, lb.z); vb.w = fmaf(rb.w - lb.w, fy, lb.w);
            v.x = fmaf(vb.x - vt.x, fx, vt.x); v.y = fmaf(vb.y - vt.y, fx, vt.y);
            v.z = fmaf(vb.z - vt.z, fx, vt.z); v.w = fmaf(vb.w - vt.w, fx, vt.w);

            half2 h01 = __floats2half2_rn(v.x, v.y);
            half2 h23 = __floats2half2_rn(v.z, v.w);
            uint2 st = make_uint2(*(uint32_t*)&h01, *(uint32_t*)&h23);
            *(uint2*)(smem + SM_A + p * ROWB + lid * 8) = st;
        }
        CP_WAIT0;
        __syncthreads();

        // ---- MMA: warp tile 32(M) x 64(N), 8 k-steps of 16 ----
        #pragma unroll
        for (int ks = 0; ks < 8; ks++) {
            const int k0b = ks * 32;       // byte offset for 16 halves
            uint32_t a[2][4];
            ldsm4(a[0], Abase + k0b);
            ldsm4(a[1], Abase + 16 * ROWB + k0b);
            #pragma unroll
            for (int q = 0; q < 4; q++) {
                uint32_t b[4];
                ldsm4(b, Bbase + q * 16 * ROWB + k0b);
                mma16816(acc[0][2 * q],     a[0], b[0], b[2]);
                mma16816(acc[0][2 * q + 1], a[0], b[1], b[3]);
                mma16816(acc[1][2 * q],     a[1], b[0], b[2]);
                mma16816(acc[1][2 * q + 1], a[1], b[1], b[3]);
            }
        }
        __syncthreads();
    }

    // ---- Epilogue: add bias, store fp32 output ----
    #pragma unroll
    for (int mt = 0; mt < 2; mt++) {
        #pragma unroll
        for (int nt = 0; nt < 8; nt++) {
            int col = wn * 64 + nt * 8 + tig * 2;
            float b0 = bsm[col], b1 = bsm[col + 1];
            int row = pix0 + wm * 32 + mt * 16 + g;
            *(float2*)(out + (size_t)row * FDIM + col) =
                make_float2(acc[mt][nt][0] + b0, acc[mt][nt][1] + b1);
            *(float2*)(out + (size_t)(row + 8) * FDIM + col) =
                make_float2(acc[mt][nt][2] + b0, acc[mt][nt][3] + b1);
        }
    }
}

extern "C" void kernel_launch(void* const* d_in, const int* in_sizes, int n_in,
                              void* d_out, int out_size) {
    const float* x   = (const float*)d_in[0];
    const float* off = (const float*)d_in[1];
    const float* Wk  = (const float*)d_in[2];
    const float* b   = (const float*)d_in[3];
    float* out = (float*)d_out;

    cudaFuncSetAttribute(deform_conv_kernel,
                         cudaFuncAttributeMaxDynamicSharedMemorySize, SMEM_BYTES);

    prep_weights_kernel<<<(KNUM * 128 * 128 + 255) / 256, 256>>>(Wk);
    deform_conv_kernel<<<NCTA, 256, SMEM_BYTES>>>(x, off, b, out);
}

// round 8
// speedup vs baseline: 1.8183x; 1.1733x over previous
#include <cuda_runtime.h>
#include <cuda_fp16.h>
#include <cstdint>

// Problem constants (fixed by setup_inputs)
#define BATCH 8
#define HDIM  64
#define WDIM  64
#define CDIM  128
#define FDIM  128
#define KNUM  9
#define NPIX  (BATCH * HDIM * WDIM)      // 32768
#define PIX_PER_CTA 128
#define NCTA  (NPIX / PIX_PER_CTA)       // 256

#define ROWB 272                          // bytes per A SMEM row (136 halves) -> conflict-free
#define TILE_BYTES (128 * ROWB)           // 34816
#define SM_A0 0
#define SM_A1 TILE_BYTES
#define SM_BIAS (2 * TILE_BYTES)          // 69632
#define SMEM_BYTES (SM_BIAS + 512)        // 70144 -> 2 CTAs/SM

// TF build(): stack(meshgrid(ij)).reshape(-1,2) pairs:
// (0,0),(0,1),(1,1),(2,2),(2,0),(1,2),(0,1),(2,0),(1,2)
static __device__ const float KOFF_I[KNUM] = {0.f, 0.f, 1.f, 2.f, 2.f, 1.f, 0.f, 2.f, 1.f};
static __device__ const float KOFF_J[KNUM] = {0.f, 1.f, 1.f, 2.f, 0.f, 2.f, 1.f, 0.f, 2.f};

// Weights pre-arranged in mma16816 B-fragment order:
// g_Wf[kn][wn(2)][ks(8)][q(4)][lane(32)] : uint4 = what ldmatrix.x4 would deliver.
// 9*2*8*4*32 uint4 = 288 KB (L2-resident, shared by all CTAs).
#define WFRAG_N (KNUM * 2 * 8 * 4 * 32)
__device__ __align__(16) uint4 g_Wf[WFRAG_N];

__global__ void prep_weights_kernel(const float* __restrict__ Wsrc) {
    int idx = blockIdx.x * 256 + threadIdx.x;
    if (idx >= WFRAG_N) return;
    int l  = idx & 31;
    int q  = (idx >> 5) & 3;
    int ks = (idx >> 7) & 7;
    int wn = (idx >> 10) & 1;
    int kn = idx >> 11;
    int n0 = wn * 64 + q * 16 + (l >> 2);  // output-feature row (N)
    int k0 = ks * 16 + 2 * (l & 3);        // channel col (K)
    // Bt[n][k] = W[kn][k][n]; pack 2 consecutive k as half2 (low = lower k).
    #define H2(nn, kk) ({ \
        __half lo_ = __float2half_rn(Wsrc[(kn * 128 + (kk)) * 128 + (nn)]); \
        __half hi_ = __float2half_rn(Wsrc[(kn * 128 + (kk) + 1) * 128 + (nn)]); \
        __half2 p_ = __halves2half2(lo_, hi_); \
        *(uint32_t*)&p_; })
    uint4 v;
    v.x = H2(n0,     k0);      // m0: rows n0..n0+7,  k 0-7  of the 16x16 block
    v.y = H2(n0 + 8, k0);      // m1: rows +8,        k 0-7
    v.z = H2(n0,     k0 + 8);  // m2: rows n0..n0+7,  k 8-15
    v.w = H2(n0 + 8, k0 + 8);  // m3: rows +8,        k 8-15
    #undef H2
    g_Wf[idx] = v;
}

__device__ __forceinline__ uint32_t smem_u32(const void* p) {
    uint32_t a;
    asm("{ .reg .u64 t; cvta.to.shared.u64 t, %1; cvt.u32.u64 %0, t; }" : "=r"(a) : "l"(p));
    return a;
}

__device__ __forceinline__ void ldsm4(uint32_t r[4], uint32_t addr) {
    asm volatile("ldmatrix.sync.aligned.m8n8.x4.shared.b16 {%0,%1,%2,%3}, [%4];"
                 : "=r"(r[0]), "=r"(r[1]), "=r"(r[2]), "=r"(r[3]) : "r"(addr));
}

__device__ __forceinline__ void mma16816(float d[4], const uint32_t a[4],
                                         uint32_t b0, uint32_t b1) {
    asm volatile(
        "mma.sync.aligned.m16n8k16.row.col.f32.f16.f16.f32 "
        "{%0,%1,%2,%3}, {%4,%5,%6,%7}, {%8,%9}, {%0,%1,%2,%3};"
        : "+f"(d[0]), "+f"(d[1]), "+f"(d[2]), "+f"(d[3])
        : "r"(a[0]), "r"(a[1]), "r"(a[2]), "r"(a[3]), "r"(b0), "r"(b1));
}

// Bilinear-sample one chunk's A tile (128 px x 128 ch, fp16) into SMEM buffer.
__device__ __forceinline__ void sample_chunk(char* smem, int abuf_off,
                                             const float* __restrict__ xin,
                                             const float* __restrict__ off,
                                             int pix0, int n, int wid, int lid) {
    const float ki = KOFF_I[n];
    const float kj = KOFF_J[n];
    #pragma unroll 2
    for (int i = 0; i < 16; i++) {
        int p = wid * 16 + i;
        int P = pix0 + p;
        int bb = P >> 12, hh = (P >> 6) & 63, ww = P & 63;
        float offr = __ldg(&off[P * 18 + 2 * n]);
        float offc = __ldg(&off[P * 18 + 2 * n + 1]);
        float y  = fminf(fmaxf((float)(hh - 1) + ki + offr, 0.0f), 63.0f);
        float xf = fminf(fmaxf((float)(ww - 1) + kj + offc, 0.0f), 63.0f);
        float y0f = floorf(y), x0f = floorf(xf);
        int y0 = (int)y0f, y1 = (int)ceilf(y);
        int x0 = (int)x0f, x1 = (int)ceilf(xf);
        float fy = y - y0f, fx = xf - x0f;

        const float4* base = (const float4*)xin + (size_t)bb * 131072;
        float4 lt = __ldg(&base[(y0 * 64 + x0) * 32 + lid]);
        float4 rt = __ldg(&base[(y1 * 64 + x0) * 32 + lid]);
        float4 lb = __ldg(&base[(y0 * 64 + x1) * 32 + lid]);
        float4 rb = __ldg(&base[(y1 * 64 + x1) * 32 + lid]);

        float4 vt, vb, v;
        vt.x = fmaf(rt.x - lt.x, fy, lt.x); vt.y = fmaf(rt.y - lt.y, fy, lt.y);
        vt.z = fmaf(rt.z - lt.z, fy, lt.z); vt.w = fmaf(rt.w - lt.w, fy, lt.w);
        vb.x = fmaf(rb.x - lb.x, fy, lb.x); vb.y = fmaf(rb.y - lb.y, fy, lb.y);
        vb.z = fmaf(rb.z - lb.z, fy, lb.z); vb.w = fmaf(rb.w - lb.w, fy, lb.w);
        v.x = fmaf(vb.x - vt.x, fx, vt.x); v.y = fmaf(vb.y - vt.y, fx, vt.y);
        v.z = fmaf(vb.z - vt.z, fx, vt.z); v.w = fmaf(vb.w - vt.w, fx, vt.w);

        half2 h01 = __floats2half2_rn(v.x, v.y);
        half2 h23 = __floats2half2_rn(v.z, v.w);
        uint2 st = make_uint2(*(uint32_t*)&h01, *(uint32_t*)&h23);
        *(uint2*)(smem + abuf_off + p * ROWB + lid * 8) = st;
    }
}

__global__ __launch_bounds__(256, 2)
void deform_conv_kernel(const float* __restrict__ xin,
                        const float* __restrict__ off,
                        const float* __restrict__ bias,
                        float* __restrict__ out) {
    extern __shared__ char smem[];
    uint32_t sb = smem_u32(smem);
    float* bsm = (float*)(smem + SM_BIAS);

    const int tid = threadIdx.x;
    const int wid = tid >> 5;
    const int lid = tid & 31;
    const int g   = lid >> 2;
    const int tig = lid & 3;
    const int wm  = wid & 3;    // warp row block (32 pixels)
    const int wn  = wid >> 2;   // warp col block (64 F)
    const int pix0 = blockIdx.x * PIX_PER_CTA;

    if (tid < 128) bsm[tid] = bias[tid];

    float acc[2][8][4];
    #pragma unroll
    for (int mt = 0; mt < 2; mt++)
        #pragma unroll
        for (int nt = 0; nt < 8; nt++)
            #pragma unroll
            for (int q = 0; q < 4; q++) acc[mt][nt][q] = 0.0f;

    // ---- Prologue: sample chunk 0 into A0 ----
    sample_chunk(smem, SM_A0, xin, off, pix0, 0, wid, lid);
    __syncthreads();

    int cur = 0;
    for (int n = 0; n < KNUM; n++) {
        const uint32_t Abase = sb + (cur ? SM_A1 : SM_A0)
                             + (wm * 32 + (lid & 15)) * ROWB + (lid >> 4) * 16;

        // ---- MMA: warp tile 32(M) x 64(N), B frags via direct LDG (prefetched) ----
        {
            const uint4* wb = g_Wf + ((n * 2 + wn) * 8) * 4 * 32 + lid;
            uint4 bq[4];
            #pragma unroll
            for (int q = 0; q < 4; q++) bq[q] = __ldg(wb + q * 32);
            #pragma unroll
            for (int ks = 0; ks < 8; ks++) {
                uint4 bn[4];
                if (ks < 7) {
                    #pragma unroll
                    for (int q = 0; q < 4; q++) bn[q] = __ldg(wb + ((ks + 1) * 4 + q) * 32);
                }
                const int k0b = ks * 32;
                uint32_t a[2][4];
                ldsm4(a[0], Abase + k0b);
                ldsm4(a[1], Abase + 16 * ROWB + k0b);
                #pragma unroll
                for (int q = 0; q < 4; q++) {
                    mma16816(acc[0][2 * q],     a[0], bq[q].x, bq[q].z);
                    mma16816(acc[0][2 * q + 1], a[0], bq[q].y, bq[q].w);
                    mma16816(acc[1][2 * q],     a[1], bq[q].x, bq[q].z);
                    mma16816(acc[1][2 * q + 1], a[1], bq[q].y, bq[q].w);
                }
                if (ks < 7) {
                    #pragma unroll
                    for (int q = 0; q < 4; q++) bq[q] = bn[q];
                }
            }
        }

        // ---- Sample chunk n+1 into the other A buffer ----
        if (n + 1 < KNUM)
            sample_chunk(smem, cur ? SM_A0 : SM_A1, xin, off, pix0, n + 1, wid, lid);

        __syncthreads();
        cur ^= 1;
    }

    // ---- Epilogue: add bias, store fp32 output ----
    #pragma unroll
    for (int mt = 0; mt < 2; mt++) {
        #pragma unroll
        for (int nt = 0; nt < 8; nt++) {
            int col = wn * 64 + nt * 8 + tig * 2;
            float b0 = bsm[col], b1 = bsm[col + 1];
            int row = pix0 + wm * 32 + mt * 16 + g;
            *(float2*)(out + (size_t)row * FDIM + col) =
                make_float2(acc[mt][nt][0] + b0, acc[mt][nt][1] + b1);
            *(float2*)(out + (size_t)(row + 8) * FDIM + col) =
                make_float2(acc[mt][nt][2] + b0, acc[mt][nt][3] + b1);
        }
    }
}

extern "C" void kernel_launch(void* const* d_in, const int* in_sizes, int n_in,
                              void* d_out, int out_size) {
    const float* x   = (const float*)d_in[0];
    const float* off = (const float*)d_in[1];
    const float* Wk  = (const float*)d_in[2];
    const float* b   = (const float*)d_in[3];
    float* out = (float*)d_out;

    cudaFuncSetAttribute(deform_conv_kernel,
                         cudaFuncAttributeMaxDynamicSharedMemorySize, SMEM_BYTES);

    prep_weights_kernel<<<(WFRAG_N + 255) / 256, 256>>>(Wk);
    deform_conv_kernel<<<NCTA, 256, SMEM_BYTES>>>(x, off, b, out);
}